// round 10
// baseline (speedup 1.0000x reference)
#include <cuda_runtime.h>
#include <cuda_bf16.h>
#include <cstdint>
#include <math.h>

#define B_ 16
#define T_ 1024
#define D_ 1024
#define TD (T_ * D_)

typedef __nv_bfloat16 bf16;

// ---------------- scratch (device globals; no allocations) ----------------
static __device__ bf16 g_Xhi[B_ * TD], g_Xlo[B_ * TD];
static __device__ bf16 g_Wqhi[D_ * D_], g_Wqlo[D_ * D_];
static __device__ bf16 g_Wkhi[D_ * D_], g_Wklo[D_ * D_];
static __device__ bf16 g_Wvhi[D_ * D_], g_Wvlo[D_ * D_];
static __device__ bf16 g_W2hi[TD], g_W2lo[TD];
static __device__ bf16 g_N1hi[D_ * D_], g_N1lo[D_ * D_];   // N1 = (1/32) Wq.Wk^T
static __device__ bf16 g_N2hi[T_ * D_], g_N2lo[T_ * D_];   // N2 = W2.Wv^T
static __device__ bf16 g_Yhi[B_ * TD], g_Ylo[B_ * TD];     // Y  = X.N1^T
static __device__ float g_S[(size_t)B_ * T_ * T_];
static __device__ float g_u[D_];       // (1/32) Wq.bk
static __device__ float g_c[B_ * T_];  // x_t.u
static __device__ float g_r2[T_];      // bv.W2[q]
static __device__ float g_part[B_ * 64];

// ---------------- low-level helpers ----------------
__device__ __forceinline__ uint32_t smem_u32(const void* p) {
    uint32_t a;
    asm("{ .reg .u64 t; cvta.to.shared.u64 t, %1; cvt.u32.u64 %0, t; }"
        : "=r"(a) : "l"(p));
    return a;
}
__device__ __forceinline__ void cpa16(uint32_t s, const void* g) {
    asm volatile("cp.async.cg.shared.global [%0], [%1], 16;" :: "r"(s), "l"(g));
}
__device__ __forceinline__ void cpa_commit() {
    asm volatile("cp.async.commit_group;" ::: "memory");
}
__device__ __forceinline__ void cpa_wait2() {
    asm volatile("cp.async.wait_group 2;" ::: "memory");
}
__device__ __forceinline__ void cpa_wait1() {
    asm volatile("cp.async.wait_group 1;" ::: "memory");
}
__device__ __forceinline__ void cpa_wait0() {
    asm volatile("cp.async.wait_group 0;" ::: "memory");
}
__device__ __forceinline__ void ldsm4(uint32_t (&r)[4], uint32_t addr) {
    asm volatile("ldmatrix.sync.aligned.m8n8.x4.shared.b16 {%0,%1,%2,%3}, [%4];"
        : "=r"(r[0]), "=r"(r[1]), "=r"(r[2]), "=r"(r[3]) : "r"(addr));
}
__device__ __forceinline__ void mma16816(float* d, const uint32_t* a,
                                         uint32_t b0, uint32_t b1) {
    asm volatile(
        "mma.sync.aligned.m16n8k16.row.col.f32.bf16.bf16.f32 "
        "{%0,%1,%2,%3}, {%4,%5,%6,%7}, {%8,%9}, {%0,%1,%2,%3};"
        : "+f"(d[0]), "+f"(d[1]), "+f"(d[2]), "+f"(d[3])
        : "r"(a[0]), "r"(a[1]), "r"(a[2]), "r"(a[3]), "r"(b0), "r"(b1));
}
__device__ __forceinline__ unsigned short bfbits(bf16 h) {
    return *reinterpret_cast<unsigned short*>(&h);
}

// ---------------- merged split kernel (fp32 -> bf16 hi/lo) ----------------
// regions (float4 units): X 4194304 | Wq 262144 | Wk 262144 | Wv 262144 | Wfc 262144
#define N4_X   (B_ * TD / 4)
#define N4_W   (D_ * D_ / 4)
#define N4_ALL (N4_X + 4 * N4_W)

__global__ void split_all(const float* __restrict__ x, const float* __restrict__ Wq,
                          const float* __restrict__ Wk, const float* __restrict__ Wv,
                          const float* __restrict__ Wfc) {
    int i = blockIdx.x * blockDim.x + threadIdx.x;
    if (i >= N4_ALL) return;
    const float* src;
    bf16 *hi, *lo;
    int j = i;
    if (j < N4_X) { src = x; hi = g_Xhi; lo = g_Xlo; }
    else {
        j -= N4_X;
        if (j < N4_W)          { src = Wq;  hi = g_Wqhi; lo = g_Wqlo; }
        else if (j < 2 * N4_W) { j -= N4_W;  src = Wk;  hi = g_Wkhi; lo = g_Wklo; }
        else if (j < 3 * N4_W) { j -= 2 * N4_W; src = Wv;  hi = g_Wvhi; lo = g_Wvlo; }
        else                   { j -= 3 * N4_W; src = Wfc; hi = g_W2hi; lo = g_W2lo; }
    }
    float4 v = ((const float4*)src)[j];
    float vs[4] = {v.x, v.y, v.z, v.w};
    unsigned short hb[4], lb[4];
#pragma unroll
    for (int t = 0; t < 4; t++) {
        bf16 h = __float2bfloat16(vs[t]);
        bf16 l = __float2bfloat16(vs[t] - __bfloat162float(h));
        hb[t] = bfbits(h); lb[t] = bfbits(l);
    }
    ((ushort4*)hi)[j] = make_ushort4(hb[0], hb[1], hb[2], hb[3]);
    ((ushort4*)lo)[j] = make_ushort4(lb[0], lb[1], lb[2], lb[3]);
}

// ---------------- GEMV kernels (warp per row, fp32) ----------------
// blocks [0,128): u = (1/32) Wq.bk ; blocks [128,256): r2 = W2.bv
__global__ void gemv_ur(const float* __restrict__ Wq, const float* __restrict__ bk,
                        const float* __restrict__ Wfc, const float* __restrict__ bv) {
    int warp = threadIdx.x >> 5, lane = threadIdx.x & 31;
    const float *mat, *vec;
    float* dst;
    float scale;
    int row;
    if (blockIdx.x < 128) { mat = Wq;  vec = bk; dst = g_u;  scale = 0.03125f; row = blockIdx.x * 8 + warp; }
    else                  { mat = Wfc; vec = bv; dst = g_r2; scale = 1.0f;     row = (blockIdx.x - 128) * 8 + warp; }
    const float4* w4 = (const float4*)(mat + (size_t)row * D_);
    const float4* b4 = (const float4*)vec;
    float s = 0.f;
#pragma unroll
    for (int i = 0; i < 8; i++) {
        float4 w = w4[lane + i * 32], b = b4[lane + i * 32];
        s += w.x * b.x + w.y * b.y + w.z * b.z + w.w * b.w;
    }
#pragma unroll
    for (int o = 16; o; o >>= 1) s += __shfl_xor_sync(0xffffffffu, s, o);
    if (lane == 0) dst[row] = s * scale;
}

__global__ void gemv_c(const float* __restrict__ x) {
    int warp = threadIdx.x >> 5, lane = threadIdx.x & 31;
    int row = blockIdx.x * 8 + warp;   // 0..16383
    const float4* x4 = (const float4*)(x + (size_t)row * D_);
    const float4* u4 = (const float4*)g_u;
    float s = 0.f;
#pragma unroll
    for (int i = 0; i < 8; i++) {
        float4 w = x4[lane + i * 32], b = u4[lane + i * 32];
        s += w.x * b.x + w.y * b.y + w.z * b.z + w.w * b.w;
    }
#pragma unroll
    for (int o = 16; o; o >>= 1) s += __shfl_xor_sync(0xffffffffu, s, o);
    if (lane == 0) g_c[row] = s;
}

// ---------------- mma.sync GEMM mainloop ----------------
// CTA 128x128, 8 warps (2x4), warp tile 64x32, kt=32.
// 4-stage cp.async pipeline, prefetch distance 2, ONE barrier per ktile.
// NT: C[m][n] = sum_k A[m][k]*B[n][k]. 3-pass hi/lo bf16 emulation, fp32 acc.
#define LDB 80          // padded bytes per 64B row -> conflict-free ldmatrix
#define OPB (128 * LDB) // 10240 bytes per operand per stage
#define STAGE (4 * OPB) // 40960
#define NSTAGE 4
#define DYN_BYTES (NSTAGE * STAGE)   // 163840

__device__ __forceinline__ void load_stage(uint32_t sb,
        const bf16* __restrict__ Ahi, const bf16* __restrict__ Alo,
        const bf16* __restrict__ Bhi, const bf16* __restrict__ Blo,
        int rowBase, int colBase, int kt, int tid) {
    const bf16* srcs[4] = {Ahi, Alo, Bhi, Blo};
#pragma unroll
    for (int op = 0; op < 4; op++) {
        int rb = (op < 2) ? rowBase : colBase;
        const bf16* s = srcs[op];
#pragma unroll
        for (int i = 0; i < 2; i++) {
            int chunk = tid + i * 256;   // 0..511
            int row = chunk >> 2, c = chunk & 3;
            cpa16(sb + op * OPB + row * LDB + c * 16,
                  s + (size_t)(rb + row) * D_ + kt * 32 + c * 8);
        }
    }
}

__device__ __forceinline__ void gemm_ml(uint32_t sbase,
        const bf16* __restrict__ Ahi, const bf16* __restrict__ Alo,
        const bf16* __restrict__ Bhi, const bf16* __restrict__ Blo,
        int rowBase, int colBase, int tid, float acc[4][4][4]) {
    const int lane = tid & 31, wid = tid >> 5;
    const int wm = wid & 1, wn = wid >> 1;
    const int lrow = lane & 15;
    const int lcol = (lane >> 4) * 16;

#pragma unroll
    for (int im = 0; im < 4; im++)
#pragma unroll
        for (int in = 0; in < 4; in++)
#pragma unroll
            for (int j = 0; j < 4; j++) acc[im][in][j] = 0.f;

    load_stage(sbase, Ahi, Alo, Bhi, Blo, rowBase, colBase, 0, tid);
    cpa_commit();
    load_stage(sbase + STAGE, Ahi, Alo, Bhi, Blo, rowBase, colBase, 1, tid);
    cpa_commit();

    for (int kt = 0; kt < 32; kt++) {
        if (kt + 2 < 32) {
            load_stage(sbase + (uint32_t)((kt + 2) & 3) * STAGE,
                       Ahi, Alo, Bhi, Blo, rowBase, colBase, kt + 2, tid);
            cpa_commit();
            cpa_wait2();           // pending: kt..kt+2 -> kt complete
        } else if (kt == 30) {
            cpa_wait1();           // pending: 30,31 -> 30 complete
        } else {
            cpa_wait0();           // kt == 31
        }
        __syncthreads();           // single barrier per ktile (4-stage, P=2: safe)

        uint32_t st = sbase + (uint32_t)(kt & 3) * STAGE;
        uint32_t aA = st + (wm * 64 + lrow) * LDB + lcol;
        uint32_t aB = st + 2 * OPB + (wn * 32 + lrow) * LDB + lcol;
#pragma unroll
        for (int kk = 0; kk < 2; kk++) {
            uint32_t bh[2][4], bl[2][4];
#pragma unroll
            for (int g = 0; g < 2; g++) {
                ldsm4(bh[g], aB + g * 16 * LDB + kk * 32);
                ldsm4(bl[g], aB + OPB + g * 16 * LDB + kk * 32);
            }
#pragma unroll
            for (int im = 0; im < 4; im++) {
                uint32_t ah[4], al[4];
                ldsm4(ah, aA + im * 16 * LDB + kk * 32);
                ldsm4(al, aA + OPB + im * 16 * LDB + kk * 32);
#pragma unroll
                for (int g = 0; g < 2; g++) {
                    mma16816(acc[im][g * 2 + 0], ah, bh[g][0], bh[g][2]);
                    mma16816(acc[im][g * 2 + 1], ah, bh[g][1], bh[g][3]);
                }
#pragma unroll
                for (int g = 0; g < 2; g++) {
                    mma16816(acc[im][g * 2 + 0], ah, bl[g][0], bl[g][2]);
                    mma16816(acc[im][g * 2 + 1], ah, bl[g][1], bl[g][3]);
                }
#pragma unroll
                for (int g = 0; g < 2; g++) {
                    mma16816(acc[im][g * 2 + 0], al, bh[g][0], bh[g][2]);
                    mma16816(acc[im][g * 2 + 1], al, bh[g][1], bh[g][3]);
                }
            }
        }
    }
}

// ---------------- generic NT gemm -> scaled bf16 hi/lo output -------------
// job 0: N1 = Wq . Wk^T * 1/32 ; job 1: N2 = W2 . Wv^T ; job 2: Y = X . N1^T
__device__ __forceinline__ void get_job(int job,
        const bf16*& Ahi, const bf16*& Alo, const bf16*& Bhi, const bf16*& Blo,
        bf16*& Ohi, bf16*& Olo, float& scale) {
    if (job == 0) {
        Ahi = g_Wqhi; Alo = g_Wqlo; Bhi = g_Wkhi; Blo = g_Wklo;
        Ohi = g_N1hi; Olo = g_N1lo; scale = 0.03125f;
    } else if (job == 1) {
        Ahi = g_W2hi; Alo = g_W2lo; Bhi = g_Wvhi; Blo = g_Wvlo;
        Ohi = g_N2hi; Olo = g_N2lo; scale = 1.0f;
    } else {
        Ahi = g_Xhi; Alo = g_Xlo; Bhi = g_N1hi; Blo = g_N1lo;
        Ohi = g_Yhi; Olo = g_Ylo; scale = 1.0f;
    }
}

__global__ void __launch_bounds__(256, 1)
gemm_split(int job) {
    extern __shared__ char dyn[];
    uint32_t sbase = smem_u32(dyn);
    const int tid = threadIdx.x;
    const int lane = tid & 31, wid = tid >> 5;
    const int wm = wid & 1, wn = wid >> 1;
    const int rowBase = blockIdx.y * 128, colBase = blockIdx.x * 128;

    const bf16 *Ahi, *Alo, *Bhi, *Blo;
    bf16 *Ohi, *Olo;
    float scale;
    get_job(job, Ahi, Alo, Bhi, Blo, Ohi, Olo, scale);

    float acc[4][4][4];
    gemm_ml(sbase, Ahi, Alo, Bhi, Blo, rowBase, colBase, tid, acc);

#pragma unroll
    for (int in = 0; in < 4; in++) {
        int col = colBase + wn * 32 + in * 8 + (lane & 3) * 2;
#pragma unroll
        for (int im = 0; im < 4; im++) {
            int row0 = rowBase + wm * 64 + im * 16 + (lane >> 2);
            float v00 = acc[im][in][0] * scale;
            float v01 = acc[im][in][1] * scale;
            float v10 = acc[im][in][2] * scale;
            float v11 = acc[im][in][3] * scale;
            bf16 h00 = __float2bfloat16(v00), h01 = __float2bfloat16(v01);
            bf16 h10 = __float2bfloat16(v10), h11 = __float2bfloat16(v11);
            bf16 l00 = __float2bfloat16(v00 - __bfloat162float(h00));
            bf16 l01 = __float2bfloat16(v01 - __bfloat162float(h01));
            bf16 l10 = __float2bfloat16(v10 - __bfloat162float(h10));
            bf16 l11 = __float2bfloat16(v11 - __bfloat162float(h11));
            size_t o0 = (size_t)row0 * D_ + col;
            size_t o1 = (size_t)(row0 + 8) * D_ + col;
            *(ushort2*)(Ohi + o0) = make_ushort2(bfbits(h00), bfbits(h01));
            *(ushort2*)(Olo + o0) = make_ushort2(bfbits(l00), bfbits(l01));
            *(ushort2*)(Ohi + o1) = make_ushort2(bfbits(h10), bfbits(h11));
            *(ushort2*)(Olo + o1) = make_ushort2(bfbits(l10), bfbits(l11));
        }
    }
}

// ---------------- scores: ST[b,k,q] = Y_b[k] . X_b[q] + c_b[q] ------------
__global__ void __launch_bounds__(256, 1)
st_mma() {
    extern __shared__ char dyn[];
    uint32_t sbase = smem_u32(dyn);
    const int tid = threadIdx.x;
    const int lane = tid & 31, wid = tid >> 5;
    const int wm = wid & 1, wn = wid >> 1;
    const int b = blockIdx.z;
    const int rowBase = blockIdx.y * 128, colBase = blockIdx.x * 128;

    float acc[4][4][4];
    gemm_ml(sbase, g_Yhi + (size_t)b * TD, g_Ylo + (size_t)b * TD,
            g_Xhi + (size_t)b * TD, g_Xlo + (size_t)b * TD,
            rowBase, colBase, tid, acc);

    float* __restrict__ S = g_S + (size_t)b * T_ * T_;
    const float* __restrict__ c = g_c + (size_t)b * T_;
#pragma unroll
    for (int in = 0; in < 4; in++) {
        int col = colBase + wn * 32 + in * 8 + (lane & 3) * 2;
        float2 cc = *(const float2*)(c + col);
#pragma unroll
        for (int im = 0; im < 4; im++) {
            int row0 = rowBase + wm * 64 + im * 16 + (lane >> 2);
            *(float2*)(S + (size_t)row0 * T_ + col) =
                make_float2(acc[im][in][0] + cc.x, acc[im][in][1] + cc.y);
            *(float2*)(S + (size_t)(row0 + 8) * T_ + col) =
                make_float2(acc[im][in][2] + cc.x, acc[im][in][3] + cc.y);
        }
    }
}

// ---------------- softmax over rows of ST (fp32) --------------------------
__global__ void softmax_kernel() {
    const int warp = threadIdx.x >> 5, lane = threadIdx.x & 31;
    const size_t row = (size_t)blockIdx.x * 8 + warp;
    float* p = g_S + row * T_;
    float4 v[8];
#pragma unroll
    for (int i = 0; i < 8; i++) v[i] = *(const float4*)(p + (lane + 32 * i) * 4);
    float m = -3.4e38f;
#pragma unroll
    for (int i = 0; i < 8; i++)
        m = fmaxf(m, fmaxf(fmaxf(v[i].x, v[i].y), fmaxf(v[i].z, v[i].w)));
#pragma unroll
    for (int o = 16; o; o >>= 1) m = fmaxf(m, __shfl_xor_sync(0xffffffffu, m, o));
    float s = 0.f;
#pragma unroll
    for (int i = 0; i < 8; i++) {
        v[i].x = expf(v[i].x - m); v[i].y = expf(v[i].y - m);
        v[i].z = expf(v[i].z - m); v[i].w = expf(v[i].w - m);
        s += v[i].x + v[i].y + v[i].z + v[i].w;
    }
#pragma unroll
    for (int o = 16; o; o >>= 1) s += __shfl_xor_sync(0xffffffffu, s, o);
    const float inv = 1.0f / s;
#pragma unroll
    for (int i = 0; i < 8; i++) {
        v[i].x *= inv; v[i].y *= inv; v[i].z *= inv; v[i].w *= inv;
        *(float4*)(p + (lane + 32 * i) * 4) = v[i];
    }
}

// ---------------- dot: sum (X_b . N2^T + r2[q]) * attnT[b,k,q] ------------
__global__ void __launch_bounds__(256, 1)
dot_mma() {
    extern __shared__ char dyn[];
    __shared__ float red[256];
    uint32_t sbase = smem_u32(dyn);
    const int tid = threadIdx.x;
    const int lane = tid & 31, wid = tid >> 5;
    const int wm = wid & 1, wn = wid >> 1;
    const int b = blockIdx.z;
    const int rowBase = blockIdx.y * 128, colBase = blockIdx.x * 128;

    float acc[4][4][4];
    gemm_ml(sbase, g_Xhi + (size_t)b * TD, g_Xlo + (size_t)b * TD,
            g_N2hi, g_N2lo, rowBase, colBase, tid, acc);

    const float* __restrict__ S = g_S + (size_t)b * T_ * T_;
    float lsum = 0.f;
#pragma unroll
    for (int in = 0; in < 4; in++) {
        int col = colBase + wn * 32 + in * 8 + (lane & 3) * 2;
        float2 rr = *(const float2*)(g_r2 + col);
#pragma unroll
        for (int im = 0; im < 4; im++) {
            int row0 = rowBase + wm * 64 + im * 16 + (lane >> 2);
            float2 s0 = *(const float2*)(S + (size_t)row0 * T_ + col);
            float2 s1 = *(const float2*)(S + (size_t)(row0 + 8) * T_ + col);
            lsum += (acc[im][in][0] + rr.x) * s0.x + (acc[im][in][1] + rr.y) * s0.y
                  + (acc[im][in][2] + rr.x) * s1.x + (acc[im][in][3] + rr.y) * s1.y;
        }
    }
    red[tid] = lsum;
    __syncthreads();
#pragma unroll
    for (int s = 128; s > 0; s >>= 1) {
        if (tid < s) red[tid] += red[tid + s];
        __syncthreads();
    }
    if (tid == 0) g_part[b * 64 + blockIdx.y * 8 + blockIdx.x] = red[0];
}

__global__ void final_kernel(const float* __restrict__ bfc, float* __restrict__ out) {
    const int b = blockIdx.x;
    const int tid = threadIdx.x;  // 64
    float v = g_part[b * 64 + tid];
#pragma unroll
    for (int o = 16; o; o >>= 1) v += __shfl_xor_sync(0xffffffffu, v, o);
    __shared__ float sh[2];
    if ((tid & 31) == 0) sh[tid >> 5] = v;
    __syncthreads();
    if (tid == 0) out[b] = sh[0] + sh[1] + bfc[0];
}

// ---------------- launch ----------------
extern "C" void kernel_launch(void* const* d_in, const int* in_sizes, int n_in,
                              void* d_out, int out_size) {
    (void)in_sizes; (void)n_in; (void)out_size;
    const float* x   = (const float*)d_in[0];
    const float* Wq  = (const float*)d_in[1];
    const float* Wk  = (const float*)d_in[3];
    const float* bk  = (const float*)d_in[4];
    const float* Wv  = (const float*)d_in[5];
    const float* bv  = (const float*)d_in[6];
    const float* Wfc = (const float*)d_in[7];
    const float* bfc = (const float*)d_in[8];
    float* out = (float*)d_out;

    cudaFuncSetAttribute(gemm_split, cudaFuncAttributeMaxDynamicSharedMemorySize, DYN_BYTES);
    cudaFuncSetAttribute(st_mma,     cudaFuncAttributeMaxDynamicSharedMemorySize, DYN_BYTES);
    cudaFuncSetAttribute(dot_mma,    cudaFuncAttributeMaxDynamicSharedMemorySize, DYN_BYTES);

    // Launch order arranged so OUR index 3 (= ncu capture slot) is the big Y GEMM.
    split_all<<<(N4_ALL + 255) / 256, 256>>>(x, Wq, Wk, Wv, Wfc);        // 0
    gemm_split<<<dim3(8, 8), 256, DYN_BYTES>>>(0);                        // 1: N1
    gemv_ur<<<256, 256>>>(Wq, bk, Wfc, bv);                               // 2: u, r2
    gemm_split<<<dim3(8, 128), 256, DYN_BYTES>>>(2);                      // 3: Y  <- profiled
    gemv_c<<<B_ * T_ / 8, 256>>>(x);                                      // 4: c
    gemm_split<<<dim3(8, 8), 256, DYN_BYTES>>>(1);                        // 5: N2

    dim3 gs(8, 8, B_);
    st_mma<<<gs, 256, DYN_BYTES>>>();                                     // 6
    softmax_kernel<<<(B_ * T_) / 8, 256>>>();                             // 7
    dot_mma<<<gs, 256, DYN_BYTES>>>();                                    // 8
    final_kernel<<<B_, 64>>>(bfc, out);                                   // 9
}

// round 12
// speedup vs baseline: 1.1429x; 1.1429x over previous
#include <cuda_runtime.h>
#include <cuda_bf16.h>
#include <cstdint>
#include <math.h>

#define B_ 16
#define T_ 1024
#define D_ 1024
#define TD (T_ * D_)

typedef __nv_bfloat16 bf16;

// ---------------- scratch (device globals; no allocations) ----------------
static __device__ bf16 g_Xhi[B_ * TD], g_Xlo[B_ * TD];
static __device__ bf16 g_Wqhi[D_ * D_], g_Wqlo[D_ * D_];
static __device__ bf16 g_Wkhi[D_ * D_], g_Wklo[D_ * D_];
static __device__ bf16 g_Wvhi[D_ * D_], g_Wvlo[D_ * D_];
static __device__ bf16 g_W2hi[TD], g_W2lo[TD];
static __device__ bf16 g_N1hi[D_ * D_], g_N1lo[D_ * D_];   // N1 = (1/32) Wq.Wk^T
static __device__ bf16 g_N2hi[T_ * D_], g_N2lo[T_ * D_];   // N2 = W2.Wv^T
static __device__ bf16 g_Yhi[B_ * TD], g_Ylo[B_ * TD];     // Y  = X.N1^T
static __device__ float g_S[(size_t)B_ * T_ * T_];
static __device__ float g_u[D_];       // (1/32) Wq.bk
static __device__ float g_c[B_ * T_];  // x_t.u
static __device__ float g_r2[T_];      // bv.W2[q]
static __device__ float g_part[B_ * 64];

// ---------------- low-level helpers ----------------
__device__ __forceinline__ uint32_t smem_u32(const void* p) {
    uint32_t a;
    asm("{ .reg .u64 t; cvta.to.shared.u64 t, %1; cvt.u32.u64 %0, t; }"
        : "=r"(a) : "l"(p));
    return a;
}
__device__ __forceinline__ void cpa16(uint32_t s, const void* g) {
    asm volatile("cp.async.cg.shared.global [%0], [%1], 16;" :: "r"(s), "l"(g));
}
__device__ __forceinline__ void cpa_commit() {
    asm volatile("cp.async.commit_group;" ::: "memory");
}
__device__ __forceinline__ void cpa_wait1() {
    asm volatile("cp.async.wait_group 1;" ::: "memory");
}
__device__ __forceinline__ void cpa_wait0() {
    asm volatile("cp.async.wait_group 0;" ::: "memory");
}
__device__ __forceinline__ void ldsm4(uint32_t (&r)[4], uint32_t addr) {
    asm volatile("ldmatrix.sync.aligned.m8n8.x4.shared.b16 {%0,%1,%2,%3}, [%4];"
        : "=r"(r[0]), "=r"(r[1]), "=r"(r[2]), "=r"(r[3]) : "r"(addr));
}
__device__ __forceinline__ void mma16816(float* d, const uint32_t* a,
                                         uint32_t b0, uint32_t b1) {
    asm volatile(
        "mma.sync.aligned.m16n8k16.row.col.f32.bf16.bf16.f32 "
        "{%0,%1,%2,%3}, {%4,%5,%6,%7}, {%8,%9}, {%0,%1,%2,%3};"
        : "+f"(d[0]), "+f"(d[1]), "+f"(d[2]), "+f"(d[3])
        : "r"(a[0]), "r"(a[1]), "r"(a[2]), "r"(a[3]), "r"(b0), "r"(b1));
}
__device__ __forceinline__ unsigned short bfbits(bf16 h) {
    return *reinterpret_cast<unsigned short*>(&h);
}

// ---------------- merged split kernel (fp32 -> bf16 hi/lo) ----------------
#define N4_X   (B_ * TD / 4)
#define N4_W   (D_ * D_ / 4)
#define N4_ALL (N4_X + 4 * N4_W)

__global__ void split_all(const float* __restrict__ x, const float* __restrict__ Wq,
                          const float* __restrict__ Wk, const float* __restrict__ Wv,
                          const float* __restrict__ Wfc) {
    int i = blockIdx.x * blockDim.x + threadIdx.x;
    if (i >= N4_ALL) return;
    const float* src;
    bf16 *hi, *lo;
    int j = i;
    if (j < N4_X) { src = x; hi = g_Xhi; lo = g_Xlo; }
    else {
        j -= N4_X;
        if (j < N4_W)          { src = Wq;  hi = g_Wqhi; lo = g_Wqlo; }
        else if (j < 2 * N4_W) { j -= N4_W;  src = Wk;  hi = g_Wkhi; lo = g_Wklo; }
        else if (j < 3 * N4_W) { j -= 2 * N4_W; src = Wv;  hi = g_Wvhi; lo = g_Wvlo; }
        else                   { j -= 3 * N4_W; src = Wfc; hi = g_W2hi; lo = g_W2lo; }
    }
    float4 v = ((const float4*)src)[j];
    float vs[4] = {v.x, v.y, v.z, v.w};
    unsigned short hb[4], lb[4];
#pragma unroll
    for (int t = 0; t < 4; t++) {
        bf16 h = __float2bfloat16(vs[t]);
        bf16 l = __float2bfloat16(vs[t] - __bfloat162float(h));
        hb[t] = bfbits(h); lb[t] = bfbits(l);
    }
    ((ushort4*)hi)[j] = make_ushort4(hb[0], hb[1], hb[2], hb[3]);
    ((ushort4*)lo)[j] = make_ushort4(lb[0], lb[1], lb[2], lb[3]);
}

// ---------------- GEMV kernels (warp per row, fp32) ----------------
__global__ void gemv_ur(const float* __restrict__ Wq, const float* __restrict__ bk,
                        const float* __restrict__ Wfc, const float* __restrict__ bv) {
    int warp = threadIdx.x >> 5, lane = threadIdx.x & 31;
    const float *mat, *vec;
    float* dst;
    float scale;
    int row;
    if (blockIdx.x < 128) { mat = Wq;  vec = bk; dst = g_u;  scale = 0.03125f; row = blockIdx.x * 8 + warp; }
    else                  { mat = Wfc; vec = bv; dst = g_r2; scale = 1.0f;     row = (blockIdx.x - 128) * 8 + warp; }
    const float4* w4 = (const float4*)(mat + (size_t)row * D_);
    const float4* b4 = (const float4*)vec;
    float s = 0.f;
#pragma unroll
    for (int i = 0; i < 8; i++) {
        float4 w = w4[lane + i * 32], b = b4[lane + i * 32];
        s += w.x * b.x + w.y * b.y + w.z * b.z + w.w * b.w;
    }
#pragma unroll
    for (int o = 16; o; o >>= 1) s += __shfl_xor_sync(0xffffffffu, s, o);
    if (lane == 0) dst[row] = s * scale;
}

__global__ void gemv_c(const float* __restrict__ x) {
    int warp = threadIdx.x >> 5, lane = threadIdx.x & 31;
    int row = blockIdx.x * 8 + warp;   // 0..16383
    const float4* x4 = (const float4*)(x + (size_t)row * D_);
    const float4* u4 = (const float4*)g_u;
    float s = 0.f;
#pragma unroll
    for (int i = 0; i < 8; i++) {
        float4 w = x4[lane + i * 32], b = u4[lane + i * 32];
        s += w.x * b.x + w.y * b.y + w.z * b.z + w.w * b.w;
    }
#pragma unroll
    for (int o = 16; o; o >>= 1) s += __shfl_xor_sync(0xffffffffu, s, o);
    if (lane == 0) g_c[row] = s;
}

// ---------------- mma.sync GEMM mainloop ----------------
// CTA 128x128, 8 warps (2x4), warp tile 64x32, kt=32, 2-stage cp.async, occ 2.
// CORRECT 2-stage ordering: load kt+1 -> commit -> wait1 -> sync (visibility:
// every thread's stage-kt copies landed + barrier publishes them) -> compute kt
// -> sync (WAR: stage kt&1 free before next iteration overwrites it).
// A-fragment double buffering hides ldsm->mma latency.
// NT: C[m][n] = sum_k A[m][k]*B[n][k]. 3-pass hi/lo bf16 emulation, fp32 acc.
#define LDB 80          // padded bytes per 64B row -> conflict-free ldmatrix
#define OPB (128 * LDB) // 10240 bytes per operand per stage
#define STAGE (4 * OPB) // 40960
#define DYN_BYTES (2 * STAGE)   // 81920 -> 2 CTAs/SM

__device__ __forceinline__ void load_stage(uint32_t sb,
        const bf16* __restrict__ Ahi, const bf16* __restrict__ Alo,
        const bf16* __restrict__ Bhi, const bf16* __restrict__ Blo,
        int rowBase, int colBase, int kt, int tid) {
    const bf16* srcs[4] = {Ahi, Alo, Bhi, Blo};
#pragma unroll
    for (int op = 0; op < 4; op++) {
        int rb = (op < 2) ? rowBase : colBase;
        const bf16* s = srcs[op];
#pragma unroll
        for (int i = 0; i < 2; i++) {
            int chunk = tid + i * 256;   // 0..511
            int row = chunk >> 2, c = chunk & 3;
            cpa16(sb + op * OPB + row * LDB + c * 16,
                  s + (size_t)(rb + row) * D_ + kt * 32 + c * 8);
        }
    }
}

__device__ __forceinline__ void gemm_ml(uint32_t sbase,
        const bf16* __restrict__ Ahi, const bf16* __restrict__ Alo,
        const bf16* __restrict__ Bhi, const bf16* __restrict__ Blo,
        int rowBase, int colBase, int tid, float acc[4][4][4]) {
    const int lane = tid & 31, wid = tid >> 5;
    const int wm = wid & 1, wn = wid >> 1;
    const int lrow = lane & 15;
    const int lcol = (lane >> 4) * 16;

#pragma unroll
    for (int im = 0; im < 4; im++)
#pragma unroll
        for (int in = 0; in < 4; in++)
#pragma unroll
            for (int j = 0; j < 4; j++) acc[im][in][j] = 0.f;

    load_stage(sbase, Ahi, Alo, Bhi, Blo, rowBase, colBase, 0, tid);
    cpa_commit();

    for (int kt = 0; kt < 32; kt++) {
        if (kt + 1 < 32) {
            load_stage(sbase + ((kt + 1) & 1) * STAGE, Ahi, Alo, Bhi, Blo,
                       rowBase, colBase, kt + 1, tid);
            cpa_commit();
            cpa_wait1();          // own stage-kt copies complete
        } else {
            cpa_wait0();
        }
        __syncthreads();          // publish ALL threads' stage-kt copies

        uint32_t st = sbase + (kt & 1) * STAGE;
        uint32_t aA = st + (wm * 64 + lrow) * LDB + lcol;
        uint32_t aB = st + 2 * OPB + (wn * 32 + lrow) * LDB + lcol;
#pragma unroll
        for (int kk = 0; kk < 2; kk++) {
            uint32_t bh[2][4], bl[2][4];
            uint32_t ahb[2][4], alb[2][4];     // A fragment double buffer
            ldsm4(ahb[0], aA + kk * 32);
            ldsm4(alb[0], aA + OPB + kk * 32);
#pragma unroll
            for (int g = 0; g < 2; g++) {
                ldsm4(bh[g], aB + g * 16 * LDB + kk * 32);
                ldsm4(bl[g], aB + OPB + g * 16 * LDB + kk * 32);
            }
#pragma unroll
            for (int im = 0; im < 4; im++) {
                const int cur = im & 1, nxt = cur ^ 1;
                if (im < 3) {   // prefetch next A pair behind this im's MMAs
                    ldsm4(ahb[nxt], aA + (im + 1) * 16 * LDB + kk * 32);
                    ldsm4(alb[nxt], aA + OPB + (im + 1) * 16 * LDB + kk * 32);
                }
#pragma unroll
                for (int g = 0; g < 2; g++) {
                    mma16816(acc[im][g * 2 + 0], ahb[cur], bh[g][0], bh[g][2]);
                    mma16816(acc[im][g * 2 + 1], ahb[cur], bh[g][1], bh[g][3]);
                }
#pragma unroll
                for (int g = 0; g < 2; g++) {
                    mma16816(acc[im][g * 2 + 0], ahb[cur], bl[g][0], bl[g][2]);
                    mma16816(acc[im][g * 2 + 1], ahb[cur], bl[g][1], bl[g][3]);
                }
#pragma unroll
                for (int g = 0; g < 2; g++) {
                    mma16816(acc[im][g * 2 + 0], alb[cur], bh[g][0], bh[g][2]);
                    mma16816(acc[im][g * 2 + 1], alb[cur], bh[g][1], bh[g][3]);
                }
            }
        }
        __syncthreads();          // stage kt&1 fully consumed -> safe to overwrite
    }
}

// ---------------- generic NT gemm -> scaled bf16 hi/lo output -------------
// job 0: N1 = Wq.Wk^T * 1/32 ; job 1: N2 = W2.Wv^T ; job 2: Y = X.N1^T
__device__ __forceinline__ void get_job(int job,
        const bf16*& Ahi, const bf16*& Alo, const bf16*& Bhi, const bf16*& Blo,
        bf16*& Ohi, bf16*& Olo, float& scale) {
    if (job == 0) {
        Ahi = g_Wqhi; Alo = g_Wqlo; Bhi = g_Wkhi; Blo = g_Wklo;
        Ohi = g_N1hi; Olo = g_N1lo; scale = 0.03125f;
    } else if (job == 1) {
        Ahi = g_W2hi; Alo = g_W2lo; Bhi = g_Wvhi; Blo = g_Wvlo;
        Ohi = g_N2hi; Olo = g_N2lo; scale = 1.0f;
    } else {
        Ahi = g_Xhi; Alo = g_Xlo; Bhi = g_N1hi; Blo = g_N1lo;
        Ohi = g_Yhi; Olo = g_Ylo; scale = 1.0f;
    }
}

__global__ void __launch_bounds__(256, 2)
gemm_split(int base_job) {
    extern __shared__ char dyn[];
    uint32_t sbase = smem_u32(dyn);
    const int tid = threadIdx.x;
    const int lane = tid & 31, wid = tid >> 5;
    const int wm = wid & 1, wn = wid >> 1;
    const int rowBase = blockIdx.y * 128, colBase = blockIdx.x * 128;

    const bf16 *Ahi, *Alo, *Bhi, *Blo;
    bf16 *Ohi, *Olo;
    float scale;
    get_job(base_job + blockIdx.z, Ahi, Alo, Bhi, Blo, Ohi, Olo, scale);

    float acc[4][4][4];
    gemm_ml(sbase, Ahi, Alo, Bhi, Blo, rowBase, colBase, tid, acc);

#pragma unroll
    for (int in = 0; in < 4; in++) {
        int col = colBase + wn * 32 + in * 8 + (lane & 3) * 2;
#pragma unroll
        for (int im = 0; im < 4; im++) {
            int row0 = rowBase + wm * 64 + im * 16 + (lane >> 2);
            float v00 = acc[im][in][0] * scale;
            float v01 = acc[im][in][1] * scale;
            float v10 = acc[im][in][2] * scale;
            float v11 = acc[im][in][3] * scale;
            bf16 h00 = __float2bfloat16(v00), h01 = __float2bfloat16(v01);
            bf16 h10 = __float2bfloat16(v10), h11 = __float2bfloat16(v11);
            bf16 l00 = __float2bfloat16(v00 - __bfloat162float(h00));
            bf16 l01 = __float2bfloat16(v01 - __bfloat162float(h01));
            bf16 l10 = __float2bfloat16(v10 - __bfloat162float(h10));
            bf16 l11 = __float2bfloat16(v11 - __bfloat162float(h11));
            size_t o0 = (size_t)row0 * D_ + col;
            size_t o1 = (size_t)(row0 + 8) * D_ + col;
            *(ushort2*)(Ohi + o0) = make_ushort2(bfbits(h00), bfbits(h01));
            *(ushort2*)(Olo + o0) = make_ushort2(bfbits(l00), bfbits(l01));
            *(ushort2*)(Ohi + o1) = make_ushort2(bfbits(h10), bfbits(h11));
            *(ushort2*)(Olo + o1) = make_ushort2(bfbits(l10), bfbits(l11));
        }
    }
}

// ---------------- scores: ST[b,k,q] = Y_b[k] . X_b[q] + c_b[q] ------------
__global__ void __launch_bounds__(256, 2)
st_mma() {
    extern __shared__ char dyn[];
    uint32_t sbase = smem_u32(dyn);
    const int tid = threadIdx.x;
    const int lane = tid & 31, wid = tid >> 5;
    const int wm = wid & 1, wn = wid >> 1;
    const int b = blockIdx.z;
    const int rowBase = blockIdx.y * 128, colBase = blockIdx.x * 128;

    float acc[4][4][4];
    gemm_ml(sbase, g_Yhi + (size_t)b * TD, g_Ylo + (size_t)b * TD,
            g_Xhi + (size_t)b * TD, g_Xlo + (size_t)b * TD,
            rowBase, colBase, tid, acc);

    float* __restrict__ S = g_S + (size_t)b * T_ * T_;
    const float* __restrict__ c = g_c + (size_t)b * T_;
#pragma unroll
    for (int in = 0; in < 4; in++) {
        int col = colBase + wn * 32 + in * 8 + (lane & 3) * 2;
        float2 cc = *(const float2*)(c + col);
#pragma unroll
        for (int im = 0; im < 4; im++) {
            int row0 = rowBase + wm * 64 + im * 16 + (lane >> 2);
            *(float2*)(S + (size_t)row0 * T_ + col) =
                make_float2(acc[im][in][0] + cc.x, acc[im][in][1] + cc.y);
            *(float2*)(S + (size_t)(row0 + 8) * T_ + col) =
                make_float2(acc[im][in][2] + cc.x, acc[im][in][3] + cc.y);
        }
    }
}

// ---------------- softmax over rows of ST (fp32) --------------------------
__global__ void softmax_kernel() {
    const int warp = threadIdx.x >> 5, lane = threadIdx.x & 31;
    const size_t row = (size_t)blockIdx.x * 8 + warp;
    float* p = g_S + row * T_;
    float4 v[8];
#pragma unroll
    for (int i = 0; i < 8; i++) v[i] = *(const float4*)(p + (lane + 32 * i) * 4);
    float m = -3.4e38f;
#pragma unroll
    for (int i = 0; i < 8; i++)
        m = fmaxf(m, fmaxf(fmaxf(v[i].x, v[i].y), fmaxf(v[i].z, v[i].w)));
#pragma unroll
    for (int o = 16; o; o >>= 1) m = fmaxf(m, __shfl_xor_sync(0xffffffffu, m, o));
    float s = 0.f;
#pragma unroll
    for (int i = 0; i < 8; i++) {
        v[i].x = expf(v[i].x - m); v[i].y = expf(v[i].y - m);
        v[i].z = expf(v[i].z - m); v[i].w = expf(v[i].w - m);
        s += v[i].x + v[i].y + v[i].z + v[i].w;
    }
#pragma unroll
    for (int o = 16; o; o >>= 1) s += __shfl_xor_sync(0xffffffffu, s, o);
    const float inv = 1.0f / s;
#pragma unroll
    for (int i = 0; i < 8; i++) {
        v[i].x *= inv; v[i].y *= inv; v[i].z *= inv; v[i].w *= inv;
        *(float4*)(p + (lane + 32 * i) * 4) = v[i];
    }
}

// ---------------- dot: sum (X_b . N2^T + r2[q]) * attnT[b,k,q] ------------
__global__ void __launch_bounds__(256, 2)
dot_mma() {
    extern __shared__ char dyn[];
    __shared__ float red[256];
    uint32_t sbase = smem_u32(dyn);
    const int tid = threadIdx.x;
    const int lane = tid & 31, wid = tid >> 5;
    const int wm = wid & 1, wn = wid >> 1;
    const int b = blockIdx.z;
    const int rowBase = blockIdx.y * 128, colBase = blockIdx.x * 128;

    float acc[4][4][4];
    gemm_ml(sbase, g_Xhi + (size_t)b * TD, g_Xlo + (size_t)b * TD,
            g_N2hi, g_N2lo, rowBase, colBase, tid, acc);

    const float* __restrict__ S = g_S + (size_t)b * T_ * T_;
    float lsum = 0.f;
#pragma unroll
    for (int in = 0; in < 4; in++) {
        int col = colBase + wn * 32 + in * 8 + (lane & 3) * 2;
        float2 rr = *(const float2*)(g_r2 + col);
#pragma unroll
        for (int im = 0; im < 4; im++) {
            int row0 = rowBase + wm * 64 + im * 16 + (lane >> 2);
            float2 s0 = *(const float2*)(S + (size_t)row0 * T_ + col);
            float2 s1 = *(const float2*)(S + (size_t)(row0 + 8) * T_ + col);
            lsum += (acc[im][in][0] + rr.x) * s0.x + (acc[im][in][1] + rr.y) * s0.y
                  + (acc[im][in][2] + rr.x) * s1.x + (acc[im][in][3] + rr.y) * s1.y;
        }
    }
    red[tid] = lsum;
    __syncthreads();
#pragma unroll
    for (int s = 128; s > 0; s >>= 1) {
        if (tid < s) red[tid] += red[tid + s];
        __syncthreads();
    }
    if (tid == 0) g_part[b * 64 + blockIdx.y * 8 + blockIdx.x] = red[0];
}

__global__ void final_kernel(const float* __restrict__ bfc, float* __restrict__ out) {
    const int b = blockIdx.x;
    const int tid = threadIdx.x;  // 64
    float v = g_part[b * 64 + tid];
#pragma unroll
    for (int o = 16; o; o >>= 1) v += __shfl_xor_sync(0xffffffffu, v, o);
    __shared__ float sh[2];
    if ((tid & 31) == 0) sh[tid >> 5] = v;
    __syncthreads();
    if (tid == 0) out[b] = sh[0] + sh[1] + bfc[0];
}

// ---------------- launch ----------------
extern "C" void kernel_launch(void* const* d_in, const int* in_sizes, int n_in,
                              void* d_out, int out_size) {
    (void)in_sizes; (void)n_in; (void)out_size;
    const float* x   = (const float*)d_in[0];
    const float* Wq  = (const float*)d_in[1];
    const float* Wk  = (const float*)d_in[3];
    const float* bk  = (const float*)d_in[4];
    const float* Wv  = (const float*)d_in[5];
    const float* bv  = (const float*)d_in[6];
    const float* Wfc = (const float*)d_in[7];
    const float* bfc = (const float*)d_in[8];
    float* out = (float*)d_out;

    cudaFuncSetAttribute(gemm_split, cudaFuncAttributeMaxDynamicSharedMemorySize, DYN_BYTES);
    cudaFuncSetAttribute(st_mma,     cudaFuncAttributeMaxDynamicSharedMemorySize, DYN_BYTES);
    cudaFuncSetAttribute(dot_mma,    cudaFuncAttributeMaxDynamicSharedMemorySize, DYN_BYTES);

    // Launch order keeps OUR index 3 (= ncu capture slot) on the big Y GEMM.
    split_all<<<(N4_ALL + 255) / 256, 256>>>(x, Wq, Wk, Wv, Wfc);        // 0
    gemv_ur<<<256, 256>>>(Wq, bk, Wfc, bv);                               // 1: u, r2
    gemm_split<<<dim3(8, 8, 2), 256, DYN_BYTES>>>(0);                     // 2: N1 + N2
    gemm_split<<<dim3(8, 128, 1), 256, DYN_BYTES>>>(2);                   // 3: Y  <- profiled
    gemv_c<<<B_ * T_ / 8, 256>>>(x);                                      // 4: c

    dim3 gs(8, 8, B_);
    st_mma<<<gs, 256, DYN_BYTES>>>();                                     // 5
    softmax_kernel<<<(B_ * T_) / 8, 256>>>();                             // 6
    dot_mma<<<gs, 256, DYN_BYTES>>>();                                    // 7
    final_kernel<<<B_, 64>>>(bfc, out);                                   // 8
}

// round 13
// speedup vs baseline: 2.7261x; 2.3852x over previous
#include <cuda_runtime.h>
#include <cuda_bf16.h>
#include <cuda_fp16.h>
#include <cstdint>
#include <math.h>

#define B_ 16
#define T_ 1024
#define D_ 1024
#define TD (T_ * D_)

typedef __nv_bfloat16 bf16;
typedef __half f16;

// ---------------- scratch (device globals; no allocations) ----------------
static __device__ f16  g_X16[B_ * TD];                      // fp16(x)
static __device__ bf16 g_Wqhi[D_ * D_], g_Wqlo[D_ * D_];
static __device__ bf16 g_Wkhi[D_ * D_], g_Wklo[D_ * D_];
static __device__ bf16 g_Wvhi[D_ * D_], g_Wvlo[D_ * D_];
static __device__ bf16 g_W2hi[TD], g_W2lo[TD];
static __device__ f16  g_N116[D_ * D_];                     // fp16( (1/32) Wq.Wk^T )
static __device__ f16  g_N216[TD];                          // fp16( W2.Wv^T )
static __device__ f16  g_Y16[B_ * TD];                      // fp16( X.N1^T )
static __device__ float g_S[(size_t)B_ * T_ * T_];
static __device__ float g_u[D_];       // (1/32) Wq.bk
static __device__ float g_c[B_ * T_];  // x_t.u
static __device__ float g_r2[T_];      // bv.W2[q]
static __device__ float g_part[B_ * 64];

// ---------------- low-level helpers ----------------
__device__ __forceinline__ uint32_t smem_u32(const void* p) {
    uint32_t a;
    asm("{ .reg .u64 t; cvta.to.shared.u64 t, %1; cvt.u32.u64 %0, t; }"
        : "=r"(a) : "l"(p));
    return a;
}
__device__ __forceinline__ void cpa16(uint32_t s, const void* g) {
    asm volatile("cp.async.cg.shared.global [%0], [%1], 16;" :: "r"(s), "l"(g));
}
__device__ __forceinline__ void cpa_commit() {
    asm volatile("cp.async.commit_group;" ::: "memory");
}
__device__ __forceinline__ void cpa_wait1() {
    asm volatile("cp.async.wait_group 1;" ::: "memory");
}
__device__ __forceinline__ void cpa_wait0() {
    asm volatile("cp.async.wait_group 0;" ::: "memory");
}
__device__ __forceinline__ void ldsm4(uint32_t (&r)[4], uint32_t addr) {
    asm volatile("ldmatrix.sync.aligned.m8n8.x4.shared.b16 {%0,%1,%2,%3}, [%4];"
        : "=r"(r[0]), "=r"(r[1]), "=r"(r[2]), "=r"(r[3]) : "r"(addr));
}
__device__ __forceinline__ void mma16816(float* d, const uint32_t* a,
                                         uint32_t b0, uint32_t b1) {
    asm volatile(
        "mma.sync.aligned.m16n8k16.row.col.f32.bf16.bf16.f32 "
        "{%0,%1,%2,%3}, {%4,%5,%6,%7}, {%8,%9}, {%0,%1,%2,%3};"
        : "+f"(d[0]), "+f"(d[1]), "+f"(d[2]), "+f"(d[3])
        : "r"(a[0]), "r"(a[1]), "r"(a[2]), "r"(a[3]), "r"(b0), "r"(b1));
}
__device__ __forceinline__ void mma16816h(float* d, const uint32_t* a,
                                          uint32_t b0, uint32_t b1) {
    asm volatile(
        "mma.sync.aligned.m16n8k16.row.col.f32.f16.f16.f32 "
        "{%0,%1,%2,%3}, {%4,%5,%6,%7}, {%8,%9}, {%0,%1,%2,%3};"
        : "+f"(d[0]), "+f"(d[1]), "+f"(d[2]), "+f"(d[3])
        : "r"(a[0]), "r"(a[1]), "r"(a[2]), "r"(a[3]), "r"(b0), "r"(b1));
}
__device__ __forceinline__ unsigned short bfbits(bf16 h) {
    return *reinterpret_cast<unsigned short*>(&h);
}
__device__ __forceinline__ unsigned short hbits(f16 h) {
    return *reinterpret_cast<unsigned short*>(&h);
}

// ---------------- merged split kernel ----------------
// X -> fp16 single; 4 weight matrices -> bf16 hi/lo (for exact N1/N2 folds)
#define N4_X   (B_ * TD / 4)
#define N4_W   (D_ * D_ / 4)
#define N4_ALL (N4_X + 4 * N4_W)

__global__ void split_all(const float* __restrict__ x, const float* __restrict__ Wq,
                          const float* __restrict__ Wk, const float* __restrict__ Wv,
                          const float* __restrict__ Wfc) {
    int i = blockIdx.x * blockDim.x + threadIdx.x;
    if (i >= N4_ALL) return;
    int j = i;
    if (j < N4_X) {
        float4 v = ((const float4*)x)[j];
        f16 h0 = __float2half_rn(v.x), h1 = __float2half_rn(v.y);
        f16 h2 = __float2half_rn(v.z), h3 = __float2half_rn(v.w);
        ((ushort4*)g_X16)[j] = make_ushort4(hbits(h0), hbits(h1), hbits(h2), hbits(h3));
        return;
    }
    j -= N4_X;
    const float* src;
    bf16 *hi, *lo;
    if (j < N4_W)          { src = Wq;  hi = g_Wqhi; lo = g_Wqlo; }
    else if (j < 2 * N4_W) { j -= N4_W;  src = Wk;  hi = g_Wkhi; lo = g_Wklo; }
    else if (j < 3 * N4_W) { j -= 2 * N4_W; src = Wv;  hi = g_Wvhi; lo = g_Wvlo; }
    else                   { j -= 3 * N4_W; src = Wfc; hi = g_W2hi; lo = g_W2lo; }
    float4 v = ((const float4*)src)[j];
    float vs[4] = {v.x, v.y, v.z, v.w};
    unsigned short hb[4], lb[4];
#pragma unroll
    for (int t = 0; t < 4; t++) {
        bf16 h = __float2bfloat16(vs[t]);
        bf16 l = __float2bfloat16(vs[t] - __bfloat162float(h));
        hb[t] = bfbits(h); lb[t] = bfbits(l);
    }
    ((ushort4*)hi)[j] = make_ushort4(hb[0], hb[1], hb[2], hb[3]);
    ((ushort4*)lo)[j] = make_ushort4(lb[0], lb[1], lb[2], lb[3]);
}

// ---------------- GEMV kernels (warp per row, fp32) ----------------
__global__ void gemv_ur(const float* __restrict__ Wq, const float* __restrict__ bk,
                        const float* __restrict__ Wfc, const float* __restrict__ bv) {
    int warp = threadIdx.x >> 5, lane = threadIdx.x & 31;
    const float *mat, *vec;
    float* dst;
    float scale;
    int row;
    if (blockIdx.x < 128) { mat = Wq;  vec = bk; dst = g_u;  scale = 0.03125f; row = blockIdx.x * 8 + warp; }
    else                  { mat = Wfc; vec = bv; dst = g_r2; scale = 1.0f;     row = (blockIdx.x - 128) * 8 + warp; }
    const float4* w4 = (const float4*)(mat + (size_t)row * D_);
    const float4* b4 = (const float4*)vec;
    float s = 0.f;
#pragma unroll
    for (int i = 0; i < 8; i++) {
        float4 w = w4[lane + i * 32], b = b4[lane + i * 32];
        s += w.x * b.x + w.y * b.y + w.z * b.z + w.w * b.w;
    }
#pragma unroll
    for (int o = 16; o; o >>= 1) s += __shfl_xor_sync(0xffffffffu, s, o);
    if (lane == 0) dst[row] = s * scale;
}

__global__ void gemv_c(const float* __restrict__ x) {
    int warp = threadIdx.x >> 5, lane = threadIdx.x & 31;
    int row = blockIdx.x * 8 + warp;   // 0..16383
    const float4* x4 = (const float4*)(x + (size_t)row * D_);
    const float4* u4 = (const float4*)g_u;
    float s = 0.f;
#pragma unroll
    for (int i = 0; i < 8; i++) {
        float4 w = x4[lane + i * 32], b = u4[lane + i * 32];
        s += w.x * b.x + w.y * b.y + w.z * b.z + w.w * b.w;
    }
#pragma unroll
    for (int o = 16; o; o >>= 1) s += __shfl_xor_sync(0xffffffffu, s, o);
    if (lane == 0) g_c[row] = s;
}

// ===================== 3-pass bf16 mainloop (N1/N2 only) ===================
#define LDB 80
#define OPB (128 * LDB)
#define STAGE (4 * OPB)
#define DYN_BYTES (2 * STAGE)

__device__ __forceinline__ void load_stage(uint32_t sb,
        const bf16* __restrict__ Ahi, const bf16* __restrict__ Alo,
        const bf16* __restrict__ Bhi, const bf16* __restrict__ Blo,
        int rowBase, int colBase, int kt, int tid) {
    const bf16* srcs[4] = {Ahi, Alo, Bhi, Blo};
#pragma unroll
    for (int op = 0; op < 4; op++) {
        int rb = (op < 2) ? rowBase : colBase;
        const bf16* s = srcs[op];
#pragma unroll
        for (int i = 0; i < 2; i++) {
            int chunk = tid + i * 256;
            int row = chunk >> 2, c = chunk & 3;
            cpa16(sb + op * OPB + row * LDB + c * 16,
                  s + (size_t)(rb + row) * D_ + kt * 32 + c * 8);
        }
    }
}

__device__ __forceinline__ void gemm_ml(uint32_t sbase,
        const bf16* __restrict__ Ahi, const bf16* __restrict__ Alo,
        const bf16* __restrict__ Bhi, const bf16* __restrict__ Blo,
        int rowBase, int colBase, int tid, float acc[4][4][4]) {
    const int lane = tid & 31, wid = tid >> 5;
    const int wm = wid & 1, wn = wid >> 1;
    const int lrow = lane & 15;
    const int lcol = (lane >> 4) * 16;

#pragma unroll
    for (int im = 0; im < 4; im++)
#pragma unroll
        for (int in = 0; in < 4; in++)
#pragma unroll
            for (int j = 0; j < 4; j++) acc[im][in][j] = 0.f;

    load_stage(sbase, Ahi, Alo, Bhi, Blo, rowBase, colBase, 0, tid);
    cpa_commit();

    for (int kt = 0; kt < 32; kt++) {
        if (kt + 1 < 32) {
            load_stage(sbase + ((kt + 1) & 1) * STAGE, Ahi, Alo, Bhi, Blo,
                       rowBase, colBase, kt + 1, tid);
            cpa_commit();
            cpa_wait1();
        } else {
            cpa_wait0();
        }
        __syncthreads();

        uint32_t st = sbase + (kt & 1) * STAGE;
        uint32_t aA = st + (wm * 64 + lrow) * LDB + lcol;
        uint32_t aB = st + 2 * OPB + (wn * 32 + lrow) * LDB + lcol;
#pragma unroll
        for (int kk = 0; kk < 2; kk++) {
            uint32_t bh[2][4], bl[2][4];
            uint32_t ahb[2][4], alb[2][4];
            ldsm4(ahb[0], aA + kk * 32);
            ldsm4(alb[0], aA + OPB + kk * 32);
#pragma unroll
            for (int g = 0; g < 2; g++) {
                ldsm4(bh[g], aB + g * 16 * LDB + kk * 32);
                ldsm4(bl[g], aB + OPB + g * 16 * LDB + kk * 32);
            }
#pragma unroll
            for (int im = 0; im < 4; im++) {
                const int cur = im & 1, nxt = cur ^ 1;
                if (im < 3) {
                    ldsm4(ahb[nxt], aA + (im + 1) * 16 * LDB + kk * 32);
                    ldsm4(alb[nxt], aA + OPB + (im + 1) * 16 * LDB + kk * 32);
                }
#pragma unroll
                for (int g = 0; g < 2; g++) {
                    mma16816(acc[im][g * 2 + 0], ahb[cur], bh[g][0], bh[g][2]);
                    mma16816(acc[im][g * 2 + 1], ahb[cur], bh[g][1], bh[g][3]);
                }
#pragma unroll
                for (int g = 0; g < 2; g++) {
                    mma16816(acc[im][g * 2 + 0], ahb[cur], bl[g][0], bl[g][2]);
                    mma16816(acc[im][g * 2 + 1], ahb[cur], bl[g][1], bl[g][3]);
                }
#pragma unroll
                for (int g = 0; g < 2; g++) {
                    mma16816(acc[im][g * 2 + 0], alb[cur], bh[g][0], bh[g][2]);
                    mma16816(acc[im][g * 2 + 1], alb[cur], bh[g][1], bh[g][3]);
                }
            }
        }
        __syncthreads();
    }
}

// N folds: job 0: N116 = fp16((1/32) Wq.Wk^T) ; job 1: N216 = fp16(W2.Wv^T)
__global__ void __launch_bounds__(256, 2)
gemm_split(int base_job) {
    extern __shared__ char dyn[];
    uint32_t sbase = smem_u32(dyn);
    const int tid = threadIdx.x;
    const int lane = tid & 31, wid = tid >> 5;
    const int wm = wid & 1, wn = wid >> 1;
    const int rowBase = blockIdx.y * 128, colBase = blockIdx.x * 128;

    int job = base_job + blockIdx.z;
    const bf16 *Ahi, *Alo, *Bhi, *Blo;
    f16* O;
    float scale;
    if (job == 0) {
        Ahi = g_Wqhi; Alo = g_Wqlo; Bhi = g_Wkhi; Blo = g_Wklo;
        O = g_N116; scale = 0.03125f;
    } else {
        Ahi = g_W2hi; Alo = g_W2lo; Bhi = g_Wvhi; Blo = g_Wvlo;
        O = g_N216; scale = 1.0f;
    }

    float acc[4][4][4];
    gemm_ml(sbase, Ahi, Alo, Bhi, Blo, rowBase, colBase, tid, acc);

#pragma unroll
    for (int in = 0; in < 4; in++) {
        int col = colBase + wn * 32 + in * 8 + (lane & 3) * 2;
#pragma unroll
        for (int im = 0; im < 4; im++) {
            int row0 = rowBase + wm * 64 + im * 16 + (lane >> 2);
            f16 h00 = __float2half_rn(acc[im][in][0] * scale);
            f16 h01 = __float2half_rn(acc[im][in][1] * scale);
            f16 h10 = __float2half_rn(acc[im][in][2] * scale);
            f16 h11 = __float2half_rn(acc[im][in][3] * scale);
            *(ushort2*)(O + (size_t)row0 * D_ + col) = make_ushort2(hbits(h00), hbits(h01));
            *(ushort2*)(O + (size_t)(row0 + 8) * D_ + col) = make_ushort2(hbits(h10), hbits(h11));
        }
    }
}

// ===================== single-pass fp16 mainloop (Y, S, C) =================
// CTA 128x128, 8 warps (2x4), warp tile 64x32, ktile 64 (4 x k16), 2-stage,
// occ 2. Correct double-barrier ordering. A-fragment double buffering.
#define LDB16 144            // 128B row + 16B pad -> conflict-free ldmatrix
#define OPB16 (128 * LDB16)  // 18432
#define STG16 (2 * OPB16)    // 36864 per stage (A+B)
#define DYN16 (2 * STG16)    // 73728 -> 2 CTAs/SM

__device__ __forceinline__ void load_stage16(uint32_t sb,
        const f16* __restrict__ A, const f16* __restrict__ Bm,
        int rowBase, int colBase, int kt, int tid) {
#pragma unroll
    for (int op = 0; op < 2; op++) {
        const f16* s = op ? Bm : A;
        int rb = op ? colBase : rowBase;
#pragma unroll
        for (int i = 0; i < 4; i++) {
            int chunk = tid + i * 256;   // 0..1023
            int row = chunk >> 3, c = chunk & 7;
            cpa16(sb + op * OPB16 + row * LDB16 + c * 16,
                  s + (size_t)(rb + row) * D_ + kt * 64 + c * 8);
        }
    }
}

__device__ __forceinline__ void gemm16_ml(uint32_t sbase,
        const f16* __restrict__ A, const f16* __restrict__ Bm,
        int rowBase, int colBase, int tid, float acc[4][4][4]) {
    const int lane = tid & 31, wid = tid >> 5;
    const int wm = wid & 1, wn = wid >> 1;
    const int lrow = lane & 15;
    const int lcol = (lane >> 4) * 16;

#pragma unroll
    for (int im = 0; im < 4; im++)
#pragma unroll
        for (int in = 0; in < 4; in++)
#pragma unroll
            for (int j = 0; j < 4; j++) acc[im][in][j] = 0.f;

    load_stage16(sbase, A, Bm, rowBase, colBase, 0, tid);
    cpa_commit();

    for (int kt = 0; kt < 16; kt++) {       // 16 ktiles of 64
        if (kt + 1 < 16) {
            load_stage16(sbase + ((kt + 1) & 1) * STG16, A, Bm,
                         rowBase, colBase, kt + 1, tid);
            cpa_commit();
            cpa_wait1();
        } else {
            cpa_wait0();
        }
        __syncthreads();          // publish stage kt

        uint32_t st = sbase + (kt & 1) * STG16;
        uint32_t aA = st + (wm * 64 + lrow) * LDB16 + lcol;
        uint32_t aB = st + OPB16 + (wn * 32 + lrow) * LDB16 + lcol;
#pragma unroll
        for (int kk = 0; kk < 4; kk++) {
            uint32_t bh[2][4];
            uint32_t ahb[2][4];
            ldsm4(ahb[0], aA + kk * 32);
#pragma unroll
            for (int g = 0; g < 2; g++)
                ldsm4(bh[g], aB + g * 16 * LDB16 + kk * 32);
#pragma unroll
            for (int im = 0; im < 4; im++) {
                const int cur = im & 1, nxt = cur ^ 1;
                if (im < 3)
                    ldsm4(ahb[nxt], aA + (im + 1) * 16 * LDB16 + kk * 32);
#pragma unroll
                for (int g = 0; g < 2; g++) {
                    mma16816h(acc[im][g * 2 + 0], ahb[cur], bh[g][0], bh[g][2]);
                    mma16816h(acc[im][g * 2 + 1], ahb[cur], bh[g][1], bh[g][3]);
                }
            }
        }
        __syncthreads();          // WAR: stage free
    }
}

// ---------------- Y = fp16( X16 . N116^T )  [16384 x 1024] ----------------
__global__ void __launch_bounds__(256, 2)
y16_mma() {
    extern __shared__ char dyn[];
    uint32_t sbase = smem_u32(dyn);
    const int tid = threadIdx.x;
    const int lane = tid & 31, wid = tid >> 5;
    const int wm = wid & 1, wn = wid >> 1;
    const int rowBase = blockIdx.y * 128, colBase = blockIdx.x * 128;

    float acc[4][4][4];
    gemm16_ml(sbase, g_X16, g_N116, rowBase, colBase, tid, acc);

#pragma unroll
    for (int in = 0; in < 4; in++) {
        int col = colBase + wn * 32 + in * 8 + (lane & 3) * 2;
#pragma unroll
        for (int im = 0; im < 4; im++) {
            int row0 = rowBase + wm * 64 + im * 16 + (lane >> 2);
            f16 h00 = __float2half_rn(acc[im][in][0]);
            f16 h01 = __float2half_rn(acc[im][in][1]);
            f16 h10 = __float2half_rn(acc[im][in][2]);
            f16 h11 = __float2half_rn(acc[im][in][3]);
            *(ushort2*)(g_Y16 + (size_t)row0 * D_ + col) = make_ushort2(hbits(h00), hbits(h01));
            *(ushort2*)(g_Y16 + (size_t)(row0 + 8) * D_ + col) = make_ushort2(hbits(h10), hbits(h11));
        }
    }
}

// ---------------- scores: ST[b,k,q] = Y16_b[k].X16_b[q] + c_b[q] ----------
__global__ void __launch_bounds__(256, 2)
st16_mma() {
    extern __shared__ char dyn[];
    uint32_t sbase = smem_u32(dyn);
    const int tid = threadIdx.x;
    const int lane = tid & 31, wid = tid >> 5;
    const int wm = wid & 1, wn = wid >> 1;
    const int b = blockIdx.z;
    const int rowBase = blockIdx.y * 128, colBase = blockIdx.x * 128;

    float acc[4][4][4];
    gemm16_ml(sbase, g_Y16 + (size_t)b * TD, g_X16 + (size_t)b * TD,
              rowBase, colBase, tid, acc);

    float* __restrict__ S = g_S + (size_t)b * T_ * T_;
    const float* __restrict__ c = g_c + (size_t)b * T_;
#pragma unroll
    for (int in = 0; in < 4; in++) {
        int col = colBase + wn * 32 + in * 8 + (lane & 3) * 2;
        float2 cc = *(const float2*)(c + col);
#pragma unroll
        for (int im = 0; im < 4; im++) {
            int row0 = rowBase + wm * 64 + im * 16 + (lane >> 2);
            *(float2*)(S + (size_t)row0 * T_ + col) =
                make_float2(acc[im][in][0] + cc.x, acc[im][in][1] + cc.y);
            *(float2*)(S + (size_t)(row0 + 8) * T_ + col) =
                make_float2(acc[im][in][2] + cc.x, acc[im][in][3] + cc.y);
        }
    }
}

// ---------------- softmax over rows of ST (fp32) --------------------------
__global__ void softmax_kernel() {
    const int warp = threadIdx.x >> 5, lane = threadIdx.x & 31;
    const size_t row = (size_t)blockIdx.x * 8 + warp;
    float* p = g_S + row * T_;
    float4 v[8];
#pragma unroll
    for (int i = 0; i < 8; i++) v[i] = *(const float4*)(p + (lane + 32 * i) * 4);
    float m = -3.4e38f;
#pragma unroll
    for (int i = 0; i < 8; i++)
        m = fmaxf(m, fmaxf(fmaxf(v[i].x, v[i].y), fmaxf(v[i].z, v[i].w)));
#pragma unroll
    for (int o = 16; o; o >>= 1) m = fmaxf(m, __shfl_xor_sync(0xffffffffu, m, o));
    float s = 0.f;
#pragma unroll
    for (int i = 0; i < 8; i++) {
        v[i].x = expf(v[i].x - m); v[i].y = expf(v[i].y - m);
        v[i].z = expf(v[i].z - m); v[i].w = expf(v[i].w - m);
        s += v[i].x + v[i].y + v[i].z + v[i].w;
    }
#pragma unroll
    for (int o = 16; o; o >>= 1) s += __shfl_xor_sync(0xffffffffu, s, o);
    const float inv = 1.0f / s;
#pragma unroll
    for (int i = 0; i < 8; i++) {
        v[i].x *= inv; v[i].y *= inv; v[i].z *= inv; v[i].w *= inv;
        *(float4*)(p + (lane + 32 * i) * 4) = v[i];
    }
}

// ---------------- dot: sum (X16_b . N216^T + r2[q]) * attnT[b,k,q] --------
__global__ void __launch_bounds__(256, 2)
dot16_mma() {
    extern __shared__ char dyn[];
    __shared__ float red[256];
    uint32_t sbase = smem_u32(dyn);
    const int tid = threadIdx.x;
    const int lane = tid & 31, wid = tid >> 5;
    const int wm = wid & 1, wn = wid >> 1;
    const int b = blockIdx.z;
    const int rowBase = blockIdx.y * 128, colBase = blockIdx.x * 128;

    float acc[4][4][4];
    gemm16_ml(sbase, g_X16 + (size_t)b * TD, g_N216, rowBase, colBase, tid, acc);

    const float* __restrict__ S = g_S + (size_t)b * T_ * T_;
    float lsum = 0.f;
#pragma unroll
    for (int in = 0; in < 4; in++) {
        int col = colBase + wn * 32 + in * 8 + (lane & 3) * 2;
        float2 rr = *(const float2*)(g_r2 + col);
#pragma unroll
        for (int im = 0; im < 4; im++) {
            int row0 = rowBase + wm * 64 + im * 16 + (lane >> 2);
            float2 s0 = *(const float2*)(S + (size_t)row0 * T_ + col);
            float2 s1 = *(const float2*)(S + (size_t)(row0 + 8) * T_ + col);
            lsum += (acc[im][in][0] + rr.x) * s0.x + (acc[im][in][1] + rr.y) * s0.y
                  + (acc[im][in][2] + rr.x) * s1.x + (acc[im][in][3] + rr.y) * s1.y;
        }
    }
    red[tid] = lsum;
    __syncthreads();
#pragma unroll
    for (int s = 128; s > 0; s >>= 1) {
        if (tid < s) red[tid] += red[tid + s];
        __syncthreads();
    }
    if (tid == 0) g_part[b * 64 + blockIdx.y * 8 + blockIdx.x] = red[0];
}

__global__ void final_kernel(const float* __restrict__ bfc, float* __restrict__ out) {
    const int b = blockIdx.x;
    const int tid = threadIdx.x;  // 64
    float v = g_part[b * 64 + tid];
#pragma unroll
    for (int o = 16; o; o >>= 1) v += __shfl_xor_sync(0xffffffffu, v, o);
    __shared__ float sh[2];
    if ((tid & 31) == 0) sh[tid >> 5] = v;
    __syncthreads();
    if (tid == 0) out[b] = sh[0] + sh[1] + bfc[0];
}

// ---------------- launch ----------------
extern "C" void kernel_launch(void* const* d_in, const int* in_sizes, int n_in,
                              void* d_out, int out_size) {
    (void)in_sizes; (void)n_in; (void)out_size;
    const float* x   = (const float*)d_in[0];
    const float* Wq  = (const float*)d_in[1];
    const float* Wk  = (const float*)d_in[3];
    const float* bk  = (const float*)d_in[4];
    const float* Wv  = (const float*)d_in[5];
    const float* bv  = (const float*)d_in[6];
    const float* Wfc = (const float*)d_in[7];
    const float* bfc = (const float*)d_in[8];
    float* out = (float*)d_out;

    cudaFuncSetAttribute(gemm_split, cudaFuncAttributeMaxDynamicSharedMemorySize, DYN_BYTES);
    cudaFuncSetAttribute(y16_mma,    cudaFuncAttributeMaxDynamicSharedMemorySize, DYN16);
    cudaFuncSetAttribute(st16_mma,   cudaFuncAttributeMaxDynamicSharedMemorySize, DYN16);
    cudaFuncSetAttribute(dot16_mma,  cudaFuncAttributeMaxDynamicSharedMemorySize, DYN16);

    // Launch order keeps OUR index 3 (= ncu capture slot) on the fp16 Y GEMM.
    split_all<<<(N4_ALL + 255) / 256, 256>>>(x, Wq, Wk, Wv, Wfc);        // 0
    gemv_ur<<<256, 256>>>(Wq, bk, Wfc, bv);                               // 1: u, r2
    gemm_split<<<dim3(8, 8, 2), 256, DYN_BYTES>>>(0);                     // 2: N1 + N2
    y16_mma<<<dim3(8, 128), 256, DYN16>>>();                              // 3: Y  <- profiled
    gemv_c<<<B_ * T_ / 8, 256>>>(x);                                      // 4: c

    dim3 gs(8, 8, B_);
    st16_mma<<<gs, 256, DYN16>>>();                                       // 5
    softmax_kernel<<<(B_ * T_) / 8, 256>>>();                             // 6
    dot16_mma<<<gs, 256, DYN16>>>();                                      // 7
    final_kernel<<<B_, 64>>>(bfc, out);                                   // 8
}